// round 12
// baseline (speedup 1.0000x reference)
#include <cuda_runtime.h>

// CARAFE: features [2,64,64,256] f32, masks [2,128,128,25] f32, k=5, group=1.
// Nearest 64->128 half-pixel => src = dst >> 1.
// R12: R10 body (float2, 5-slot rotating window, d-major taps, immediate
//      offsets, interior/border split) + per-warp mask staging (own smem copy,
//      __syncwarp only -> warps desynchronize, no block barrier) + window-fill
//      LDGs issued before mask staging so the two latency chains overlap.

#define FH 64
#define FW 64
#define C2 128     // 256 channels / 2 (float2 groups)
#define OH 128
#define OW 128
#define KK 25
#define SEGW 8

__device__ __forceinline__ void fma2s(float2& a, const float2 f, const float m) {
    a.x = fmaf(f.x, m, a.x);
    a.y = fmaf(f.y, m, a.y);
}

template<bool CHK>
__device__ __forceinline__ void carafe_body(int seg, int hs, int b,
                                            const float2* __restrict__ F,
                                            float2* __restrict__ O,
                                            const float* __restrict__ masks,
                                            float* __restrict__ smw,
                                            int c2, int lane)
{
    const int ws0 = seg * SEGW;
    const float2 z = make_float2(0.f, 0.f);

    const float2* fb = F + ((b * FH + (hs - 2)) * FW + (ws0 - 2)) * C2 + c2;

    bool rok[5];
    #pragma unroll
    for (int r = 0; r < 5; r++) {
        int hr = hs - 2 + r;
        rok[r] = CHK ? (hr >= 0 && hr < FH) : true;
    }

    // ---- window initial fill FIRST: 25 independent LDGs in flight ----
    float2 w[5][5];
    #pragma unroll
    for (int j = 0; j < 5; j++) {
        bool cok = CHK ? ((ws0 - 2 + j) >= 0 && (ws0 - 2 + j) < FW) : true;
        #pragma unroll
        for (int r = 0; r < 5; r++)
            w[r][j] = (rok[r] && cok) ? fb[(r * FW + j) * C2] : z;
    }

    // ---- per-warp mask stage (overlaps with window LDG latency) ----
    // lane = px*4 + o (px:0..7, o = oy*2+ox); copies the pixel's 25 contiguous
    // mask floats into transposed layout [px][tap][o].
    {
        const int px = lane >> 2;
        const int o  = lane & 3;
        const int oy = o >> 1;
        const int ox = o & 1;
        const float* gm = masks
            + ((b * OH + 2 * hs + oy) * OW + 2 * (ws0 + px) + ox) * KK;
        float* sm = smw + px * (KK * 4) + o;
        #pragma unroll
        for (int t = 0; t < KK; t++)
            sm[t * 4] = gm[t];
    }
    __syncwarp();

    float2* ob = O + ((b * OH + 2 * hs) * OW + 2 * ws0) * C2 + c2;

    #pragma unroll
    for (int s = 0; s < SEGW; s++) {
        const float4* __restrict__ mp = (const float4*)(smw + s * (KK * 4));

        float2 a0 = z, a1 = z, a2 = z, a3 = z;

        // d-major sweep; the slot refilled at end of iter s-1 is consumed
        // only in the last 5 taps (d=4) -> LDG latency covered.
        #pragma unroll
        for (int d = 0; d < 5; d++) {
            #pragma unroll
            for (int r = 0; r < 5; r++) {
                const float2 f = w[r][(s + d) % 5];   // compile-time slot
                const float4 m = mp[r * 5 + d];       // broadcast LDS.128
                fma2s(a0, f, m.x);
                fma2s(a1, f, m.y);
                fma2s(a2, f, m.z);
                fma2s(a3, f, m.w);
            }
        }

        ob[(2 * s) * C2]          = a0;
        ob[(2 * s + 1) * C2]      = a1;
        ob[(OW + 2 * s) * C2]     = a2;
        ob[(OW + 2 * s + 1) * C2] = a3;

        if (s < SEGW - 1) {
            const bool cok = CHK ? ((ws0 + s + 3) < FW) : true;
            #pragma unroll
            for (int r = 0; r < 5; r++)
                w[r][s % 5] = (rok[r] && cok) ? fb[(r * FW + (s + 5)) * C2] : z;
        }
    }
}

__global__ __launch_bounds__(128)
void carafe_kernel(const float* __restrict__ features,
                   const float* __restrict__ masks,
                   float* __restrict__ out)
{
    // per-warp mask copies: [warp(4)][px(8)][tap(25)][out(4)]
    __shared__ __align__(16) float smask[4][SEGW * KK * 4];

    const int tid  = threadIdx.x;
    const int lane = tid & 31;
    const int wrp  = tid >> 5;
    const int seg  = blockIdx.x;
    const int hs   = blockIdx.y;
    const int b    = blockIdx.z;

    const float2* F = (const float2*)features;
    float2* O = (float2*)out;

    const bool interior = (seg >= 1) && (seg <= 6) && (hs >= 2) && (hs <= 61);
    if (interior)
        carafe_body<false>(seg, hs, b, F, O, masks, smask[wrp], tid, lane);
    else
        carafe_body<true>(seg, hs, b, F, O, masks, smask[wrp], tid, lane);
}

extern "C" void kernel_launch(void* const* d_in, const int* in_sizes, int n_in,
                              void* d_out, int out_size) {
    const float* features = (const float*)d_in[0];
    const float* masks    = (const float*)d_in[1];
    float* out            = (float*)d_out;

    dim3 grid(FW / SEGW, FH, 2);   // (8, 64, 2) = 1024 blocks x 4 warps
    carafe_kernel<<<grid, 128>>>(features, masks, out);
}

// round 13
// speedup vs baseline: 1.2410x; 1.2410x over previous
#include <cuda_runtime.h>

// CARAFE: features [2,64,64,256] f32, masks [2,128,128,25] f32, k=5, group=1.
// Nearest 64->128 half-pixel => src = dst >> 1.
// R13: R10 body + double-buffered mask register groups. 40 groups of
//      [5 LDS.128 -> 20 FFMA]; group g computes from m[g%2] while group g+1
//      loads into m[(g+1)%2] (compile-time parity after full unroll -> no
//      copies). Every mask LDS gets ~40 cyc of FFMA before first use.

#define FH 64
#define FW 64
#define C2 128     // 256 channels / 2 (float2 groups)
#define OH 128
#define OW 128
#define KK 25
#define SEGW 8

__device__ __forceinline__ void fma2s(float2& a, const float2 f, const float m) {
    a.x = fmaf(f.x, m, a.x);
    a.y = fmaf(f.y, m, a.y);
}

template<bool CHK>
__device__ __forceinline__ void carafe_body(int seg, int hs, int b,
                                            const float2* __restrict__ F,
                                            float2* __restrict__ O,
                                            const float* __restrict__ smask,
                                            int c2)
{
    const int ws0 = seg * SEGW;
    const float2 z = make_float2(0.f, 0.f);

    const float2* fb = F + ((b * FH + (hs - 2)) * FW + (ws0 - 2)) * C2 + c2;

    bool rok[5];
    #pragma unroll
    for (int r = 0; r < 5; r++) {
        int hr = hs - 2 + r;
        rok[r] = CHK ? (hr >= 0 && hr < FH) : true;
    }

    // 5-slot rotating window: col (ws0-2+j) -> slot j (mod 5)
    float2 w[5][5];
    #pragma unroll
    for (int j = 0; j < 5; j++) {
        bool cok = CHK ? ((ws0 - 2 + j) >= 0 && (ws0 - 2 + j) < FW) : true;
        #pragma unroll
        for (int r = 0; r < 5; r++)
            w[r][j] = (rok[r] && cok) ? fb[(r * FW + j) * C2] : z;
    }

    float2* ob = O + ((b * OH + 2 * hs) * OW + 2 * ws0) * C2 + c2;

    // smask as float4[px*25 + p], p = r*5+d (source order), .xyzw = 4 outputs
    const float4* __restrict__ mp = (const float4*)smask;

    // double-buffered mask groups; all indices compile-time after unroll
    float4 m[2][5];

    // preload group g=0 (pixel 0, d=0): taps p = r*5
    #pragma unroll
    for (int r = 0; r < 5; r++)
        m[0][r] = mp[r * 5];

    #pragma unroll
    for (int s = 0; s < SEGW; s++) {
        float2 a0 = z, a1 = z, a2 = z, a3 = z;

        #pragma unroll
        for (int d = 0; d < 5; d++) {
            const int g   = s * 5 + d;        // global group index (compile-time)
            const int cur = g & 1;
            const int nxt = cur ^ 1;

            // issue next group's 5 LDS.128 before computing this group
            if (g + 1 < SEGW * 5) {
                const int sn = (d == 4) ? s + 1 : s;
                const int dn = (d == 4) ? 0 : d + 1;
                #pragma unroll
                for (int r = 0; r < 5; r++)
                    m[nxt][r] = mp[sn * KK + r * 5 + dn];
            }

            // compute group (s, d): 20 FFMA from m[cur]
            #pragma unroll
            for (int r = 0; r < 5; r++) {
                const float2 f = w[r][(s + d) % 5];   // compile-time slot
                fma2s(a0, f, m[cur][r].x);
                fma2s(a1, f, m[cur][r].y);
                fma2s(a2, f, m[cur][r].z);
                fma2s(a3, f, m[cur][r].w);
            }
        }

        ob[(2 * s) * C2]          = a0;
        ob[(2 * s + 1) * C2]      = a1;
        ob[(OW + 2 * s) * C2]     = a2;
        ob[(OW + 2 * s + 1) * C2] = a3;

        if (s < SEGW - 1) {
            // refill col (ws0+s+3) into slot s%5; consumed at iter s+1, d=4
            const bool cok = CHK ? ((ws0 + s + 3) < FW) : true;
            #pragma unroll
            for (int r = 0; r < 5; r++)
                w[r][s % 5] = (rok[r] && cok) ? fb[(r * FW + (s + 5)) * C2] : z;
        }
    }
}

__global__ __launch_bounds__(128)
void carafe_kernel(const float* __restrict__ features,
                   const float* __restrict__ masks,
                   float* __restrict__ out)
{
    // smask layout: [px(8)][p(25)][out(4)], p = r*5+d (source order)
    __shared__ __align__(16) float smask[SEGW * KK * 4];

    const int tid = threadIdx.x;
    const int seg = blockIdx.x;
    const int hs  = blockIdx.y;
    const int b   = blockIdx.z;
    const int ws0 = seg * SEGW;

    // ---- division-free mask transpose stage (R10) ----
    // tid = px*16 + o*4 + q; thread copies taps p = q+4k, immediate offsets.
    {
        const int q  = tid & 3;
        const int o  = (tid >> 2) & 3;
        const int px = tid >> 4;
        const int oy = o >> 1;
        const int ox = o & 1;

        const float* gm = masks
            + ((b * OH + 2 * hs + oy) * OW + 2 * (ws0 + px) + ox) * KK + q;
        float* sm = smask + px * (KK * 4) + q * 4 + o;

        #pragma unroll
        for (int k = 0; k < 7; k++) {
            if (k < 6 || q == 0)
                sm[k * 16] = gm[k * 4];
        }
    }
    __syncthreads();

    const float2* F = (const float2*)features;
    float2* O = (float2*)out;

    const bool interior = (seg >= 1) && (seg <= 6) && (hs >= 2) && (hs <= 61);
    if (interior)
        carafe_body<false>(seg, hs, b, F, O, smask, tid);
    else
        carafe_body<true>(seg, hs, b, F, O, smask, tid);
}

extern "C" void kernel_launch(void* const* d_in, const int* in_sizes, int n_in,
                              void* d_out, int out_size) {
    const float* features = (const float*)d_in[0];
    const float* masks    = (const float*)d_in[1];
    float* out            = (float*)d_out;

    dim3 grid(FW / SEGW, FH, 2);   // (8, 64, 2) = 1024 blocks x 4 warps
    carafe_kernel<<<grid, 128>>>(features, masks, out);
}